// round 9
// baseline (speedup 1.0000x reference)
#include <cuda_runtime.h>

typedef unsigned long long ull;

#define NSUP 25
#define CWH  3072
#define DF   640
#define MS   400
#define MQ   240
#define MKF  640
#define NRHS 16
#define CW   416
#define SPLITS_KF 8
#define NRED 625

// ---------------- device scratch ----------------
__device__ __align__(16) float g_KF[MKF * DF];                 // rows 0..399 = K
__device__ __align__(16) float g_parts[SPLITS_KF * MKF * DF];  // kf partials, then aul partials
__device__ __align__(16) float g_A2[MS * MS];
__device__ __align__(16) float g_Ba[MS * MS];      // dense B^256 at the end
__device__ __align__(16) float g_Bb[MS * MS];      // B^2
__device__ __align__(16) float g_Xa[MS * NRHS];
__device__ __align__(16) float g_Xb[MS * NRHS];
__device__ __align__(16) float g_M[2][4][MS * CW];
__device__ float g_red[1024];
__device__ float g_scal[4];
__device__ __align__(16) float g_w[NRHS * DF];
__device__ __align__(16) float g_Tt[NRHS * CWH];   // Tt[c][d] = (W @ w^T)[d][c]

// ---------------- packed f32x2 helpers ----------------
__device__ __forceinline__ ull ffma2(ull a, ull b, ull c) {
    ull d;
    asm("fma.rn.f32x2 %0, %1, %2, %3;" : "=l"(d) : "l"(a), "l"(b), "l"(c));
    return d;
}
union UF2 { float2 f; ull u; };
__device__ __forceinline__ ull pack2(float x, float y) {
    UF2 t; t.f = make_float2(x, y); return t.u;
}
__device__ __forceinline__ float2 u2f(ull v) { UF2 t; t.u = v; return t.f; }

// ============================================================
// GEMM KF (K only): S_flat(400x3072) @ W(3072x640), BM=64 BN=64 BK=16
// grid (10, 7, 8), 128 thr, 4x8 micro (f32x2), split-K partials
// ============================================================
__global__ __launch_bounds__(128) void k_gemm_kf(const float* __restrict__ S,
                                                 const float* __restrict__ W) {
    __shared__ float As[16][68];
    __shared__ float Bs[16][68];
    const int tid = threadIdx.x;
    const int n0 = blockIdx.x * 64;
    const int m0 = blockIdx.y * 64;
    const int sp = blockIdx.z;
    const int kt0 = sp * 24, kt1 = kt0 + 24;   // 192 kts / 8
    const int ty = tid >> 3, tx = tid & 7;
    ull acc[4][4];
#pragma unroll
    for (int i = 0; i < 4; i++)
#pragma unroll
        for (int u = 0; u < 4; u++) acc[i][u] = 0ull;

    for (int kt = kt0; kt < kt1; ++kt) {
        const int k0 = kt * 16;
#pragma unroll
        for (int i = 0; i < 2; i++) {
            int idx = tid + i * 128;
            int r = idx >> 2, q = idx & 3;
            int rr = m0 + r; if (rr > MS - 1) rr = MS - 1;
            float4 v = *reinterpret_cast<const float4*>(S + (size_t)rr * CWH + k0 + q * 4);
            As[q * 4 + 0][r] = v.x; As[q * 4 + 1][r] = v.y;
            As[q * 4 + 2][r] = v.z; As[q * 4 + 3][r] = v.w;
        }
#pragma unroll
        for (int i = 0; i < 2; i++) {
            int idx = tid + i * 128;
            int kk = idx >> 4, c4 = idx & 15;
            float4 v = *reinterpret_cast<const float4*>(W + (size_t)(k0 + kk) * DF + n0 + c4 * 4);
            *reinterpret_cast<float4*>(&Bs[kk][c4 * 4]) = v;
        }
        __syncthreads();
#pragma unroll
        for (int k = 0; k < 16; k++) {
            float4 a = *(const float4*)&As[k][ty * 4];
            float4 b0 = *(const float4*)&Bs[k][tx * 8];
            float4 b1 = *(const float4*)&Bs[k][tx * 8 + 4];
            ull bv[4] = { pack2(b0.x, b0.y), pack2(b0.z, b0.w),
                          pack2(b1.x, b1.y), pack2(b1.z, b1.w) };
            ull ad[4] = { pack2(a.x, a.x), pack2(a.y, a.y),
                          pack2(a.z, a.z), pack2(a.w, a.w) };
#pragma unroll
            for (int i = 0; i < 4; i++)
#pragma unroll
                for (int u = 0; u < 4; u++) acc[i][u] = ffma2(ad[i], bv[u], acc[i][u]);
        }
        __syncthreads();
    }
    float* out = g_parts + (size_t)sp * MS * DF;
#pragma unroll
    for (int i = 0; i < 4; i++) {
        int r = m0 + ty * 4 + i;
        if (r < MS) {
#pragma unroll
            for (int u = 0; u < 4; u++)
                *reinterpret_cast<ull*>(out + (size_t)r * DF + n0 + tx * 8 + 2 * u) = acc[i][u];
        }
    }
}

__global__ void k_reduce_kf() {
    int i = blockIdx.x * 256 + threadIdx.x;
    if (i >= MS * DF) return;
    const size_t T = (size_t)MS * DF;
    float s = 0.f;
#pragma unroll
    for (int p = 0; p < SPLITS_KF; p++) s += g_parts[p * T + i];
    g_KF[i] = s;
}

// ============================================================
// aul = K K^T (NT, 400x400x640) split-K=4 -> partials in g_parts
// ============================================================
__global__ __launch_bounds__(128) void k_gemm_aul() {
    __shared__ float As[16][68];
    __shared__ float Bs2[16][72];
    const int tid = threadIdx.x;
    const int n0 = blockIdx.x * 32;
    const int m0 = blockIdx.y * 64;
    const int sp = blockIdx.z;
    const int kt0 = sp * 10, kt1 = kt0 + 10;
    const int ty = tid >> 4, tx = tid & 15;
    ull acc[4][2];
#pragma unroll
    for (int i = 0; i < 4; i++) { acc[i][0] = 0ull; acc[i][1] = 0ull; }

    for (int kt = kt0; kt < kt1; ++kt) {
        const int k0 = kt * 16;
#pragma unroll
        for (int i = 0; i < 2; i++) {
            int idx = tid + i * 128;
            int r = idx >> 2, q = idx & 3;
            int rr = m0 + r; if (rr > MS - 1) rr = MS - 1;
            float4 v = *reinterpret_cast<const float4*>(g_KF + (size_t)rr * DF + k0 + q * 4);
            As[q * 4 + 0][r] = v.x; As[q * 4 + 1][r] = v.y;
            As[q * 4 + 2][r] = v.z; As[q * 4 + 3][r] = v.w;
        }
        {
            int n = tid >> 2, q = tid & 3;
            int nn = n0 + n; if (nn > MS - 1) nn = MS - 1;
            float4 v = *reinterpret_cast<const float4*>(g_KF + (size_t)nn * DF + k0 + q * 4);
            *reinterpret_cast<ull*>(&Bs2[q * 4 + 0][n * 2]) = pack2(v.x, v.x);
            *reinterpret_cast<ull*>(&Bs2[q * 4 + 1][n * 2]) = pack2(v.y, v.y);
            *reinterpret_cast<ull*>(&Bs2[q * 4 + 2][n * 2]) = pack2(v.z, v.z);
            *reinterpret_cast<ull*>(&Bs2[q * 4 + 3][n * 2]) = pack2(v.w, v.w);
        }
        __syncthreads();
#pragma unroll
        for (int k = 0; k < 16; k++) {
            float4 a0 = *(const float4*)&As[k][ty * 8];
            float4 a1 = *(const float4*)&As[k][ty * 8 + 4];
            float4 bq = *(const float4*)&Bs2[k][tx * 4];
            ull ap[4] = { pack2(a0.x, a0.y), pack2(a0.z, a0.w),
                          pack2(a1.x, a1.y), pack2(a1.z, a1.w) };
            ull b0 = pack2(bq.x, bq.y), b1 = pack2(bq.z, bq.w);
#pragma unroll
            for (int i = 0; i < 4; i++) {
                acc[i][0] = ffma2(ap[i], b0, acc[i][0]);
                acc[i][1] = ffma2(ap[i], b1, acc[i][1]);
            }
        }
        __syncthreads();
    }
    float* out = g_parts + (size_t)sp * MS * MS;
    int c = n0 + tx * 2;
    if (c < MS) {
#pragma unroll
        for (int i = 0; i < 4; i++) {
            int r0 = m0 + ty * 8 + 2 * i;
            if (r0 < MS) {
                float2 f0 = u2f(acc[i][0]);
                float2 f1 = u2f(acc[i][1]);
                *reinterpret_cast<ull*>(out + (size_t)r0 * MS + c) = pack2(f0.x, f1.x);
                *reinterpret_cast<ull*>(out + (size_t)(r0 + 1) * MS + c) = pack2(f0.y, f1.y);
            }
        }
    }
}

// ============================================================
// A2 = aul @ aul: loaders sum the 4 aul partials + add 50*delta inline
// ============================================================
__global__ __launch_bounds__(128) void k_gemm_a2() {
    __shared__ float As[16][68];
    __shared__ float Bs2[16][72];
    const int tid = threadIdx.x;
    const int n0 = blockIdx.x * 32;
    const int m0 = blockIdx.y * 64;
    const int sp = blockIdx.z;
    const int kt0 = sp * 25 / 4, kt1 = (sp + 1) * 25 / 4;
    const int ty = tid >> 4, tx = tid & 15;
    const size_t T = (size_t)MS * MS;
    ull acc[4][2];
#pragma unroll
    for (int i = 0; i < 4; i++) { acc[i][0] = 0ull; acc[i][1] = 0ull; }

    for (int kt = kt0; kt < kt1; ++kt) {
        const int k0 = kt * 16;
#pragma unroll
        for (int i = 0; i < 2; i++) {
            int idx = tid + i * 128;
            int r = idx >> 2, q = idx & 3;
            int rr = m0 + r; if (rr > MS - 1) rr = MS - 1;
            const float* base = g_parts + (size_t)rr * MS + k0 + q * 4;
            float4 v0 = *(const float4*)(base);
            float4 v1 = *(const float4*)(base + T);
            float4 v2 = *(const float4*)(base + 2 * T);
            float4 v3 = *(const float4*)(base + 3 * T);
            float e0 = v0.x + v1.x + v2.x + v3.x;
            float e1 = v0.y + v1.y + v2.y + v3.y;
            float e2 = v0.z + v1.z + v2.z + v3.z;
            float e3 = v0.w + v1.w + v2.w + v3.w;
            int cb = k0 + q * 4;
            if (rr == cb) e0 += 50.f;
            if (rr == cb + 1) e1 += 50.f;
            if (rr == cb + 2) e2 += 50.f;
            if (rr == cb + 3) e3 += 50.f;
            As[q * 4 + 0][r] = e0; As[q * 4 + 1][r] = e1;
            As[q * 4 + 2][r] = e2; As[q * 4 + 3][r] = e3;
        }
        {
            int kk = tid >> 3, c4 = tid & 7;
            int c = n0 + c4 * 4;
            int kr = k0 + kk;
            float e0 = 0.f, e1 = 0.f, e2 = 0.f, e3 = 0.f;
            if (c < MS) {
                const float* base = g_parts + (size_t)kr * MS + c;
                float4 v0 = *(const float4*)(base);
                float4 v1 = *(const float4*)(base + T);
                float4 v2 = *(const float4*)(base + 2 * T);
                float4 v3 = *(const float4*)(base + 3 * T);
                e0 = v0.x + v1.x + v2.x + v3.x;
                e1 = v0.y + v1.y + v2.y + v3.y;
                e2 = v0.z + v1.z + v2.z + v3.z;
                e3 = v0.w + v1.w + v2.w + v3.w;
                if (kr == c) e0 += 50.f;
                if (kr == c + 1) e1 += 50.f;
                if (kr == c + 2) e2 += 50.f;
                if (kr == c + 3) e3 += 50.f;
            }
            *reinterpret_cast<float4*>(&Bs2[kk][c4 * 8]) = make_float4(e0, e0, e1, e1);
            *reinterpret_cast<float4*>(&Bs2[kk][c4 * 8 + 4]) = make_float4(e2, e2, e3, e3);
        }
        __syncthreads();
#pragma unroll
        for (int k = 0; k < 16; k++) {
            float4 a0 = *(const float4*)&As[k][ty * 8];
            float4 a1 = *(const float4*)&As[k][ty * 8 + 4];
            float4 bq = *(const float4*)&Bs2[k][tx * 4];
            ull ap[4] = { pack2(a0.x, a0.y), pack2(a0.z, a0.w),
                          pack2(a1.x, a1.y), pack2(a1.z, a1.w) };
            ull b0 = pack2(bq.x, bq.y), b1 = pack2(bq.z, bq.w);
#pragma unroll
            for (int i = 0; i < 4; i++) {
                acc[i][0] = ffma2(ap[i], b0, acc[i][0]);
                acc[i][1] = ffma2(ap[i], b1, acc[i][1]);
            }
        }
        __syncthreads();
    }
    float* out = g_M[0][sp];
    int c = n0 + tx * 2;
    if (c < MS) {
#pragma unroll
        for (int i = 0; i < 4; i++) {
            int r0 = m0 + ty * 8 + 2 * i;
            if (r0 < MS) {
                float2 f0 = u2f(acc[i][0]);
                float2 f1 = u2f(acc[i][1]);
                *reinterpret_cast<ull*>(out + (size_t)r0 * MS + c) = pack2(f0.x, f1.x);
                *reinterpret_cast<ull*>(out + (size_t)(r0 + 1) * MS + c) = pack2(f0.y, f1.y);
            }
        }
    }
}

// Sum A2 partials -> g_A2 + Frobenius^2 block partials
__global__ void k_fro() {
    int i = blockIdx.x * 256 + threadIdx.x;
    float v = 0.f;
    if (i < MS * MS) {
        v = g_M[0][0][i] + g_M[0][1][i] + g_M[0][2][i] + g_M[0][3][i];
        g_A2[i] = v;
    }
    __shared__ float sh[256];
    sh[threadIdx.x] = v * v; __syncthreads();
    for (int o = 128; o > 0; o >>= 1) {
        if (threadIdx.x < o) sh[threadIdx.x] += sh[threadIdx.x + o];
        __syncthreads();
    }
    if (threadIdx.x == 0) g_red[blockIdx.x] = sh[0];
}

// omega = 2/(b+50); B^2 = I - 2wA + w^2 A2 ; X1 = 2P - w*rowblocksum(aul)
// aul consumed as partial-sum + 50*delta
__global__ void k_buildBX() {
    __shared__ float sh[256];
    float t = 0.f;
    for (int i = threadIdx.x; i < NRED; i += 256) t += g_red[i];
    sh[threadIdx.x] = t; __syncthreads();
    for (int o = 128; o > 0; o >>= 1) {
        if (threadIdx.x < o) sh[threadIdx.x] += sh[threadIdx.x + o];
        __syncthreads();
    }
    float b = sqrtf(sqrtf(sh[0])) * 1.0001f;
    if (!(b > 51.f)) b = 51.f;
    float om = 2.0f / (b + 50.0f);
    if (blockIdx.x == 0 && threadIdx.x == 0) g_scal[1] = om;

    const size_t T = (size_t)MS * MS;
    int i = blockIdx.x * 256 + threadIdx.x;
    if (i < MS * MS) {
        int r = i / MS, c = i - r * MS;
        float av = g_parts[i] + g_parts[T + i] + g_parts[2 * T + i] + g_parts[3 * T + i];
        float d = 0.f;
        if (r == c) { av += 50.f; d = 1.f; }
        float a = av * om;
        float a2 = g_A2[i] * om * om;
        g_Bb[i] = d - 2.f * a + a2;
    } else if (i < MS * MS + MS * NRHS) {
        int idx = i - MS * MS;
        int j = idx >> 4, c = idx & 15;
        float s = ((j / NSUP) == c) ? 2.f : 0.f;
        const float* row = g_parts + (size_t)j * MS + c * NSUP;
        float u = 0.f;
#pragma unroll
        for (int q = 0; q < NSUP; q++)
            u += row[q] + row[q + T] + row[q + 2 * T] + row[q + 3 * T];
        if ((j / NSUP) == c) u += 50.f;   // diagonal inside this 25-block
        g_Xa[idx] = s - u * om;
    }
}

// ============================================================
// Chain iteration, split-K=4, partial in / partial out.
// ============================================================
__global__ __launch_bounds__(128) void k_iter(int first, int src, int dst) {
    __shared__ float As[16][68];
    __shared__ float Bs2[16][72];
    const int tid = threadIdx.x;
    const int n0 = blockIdx.x * 32;
    const int m0 = blockIdx.y * 64;
    const int sp = blockIdx.z;
    const int kt0 = sp * 25 / 4, kt1 = (sp + 1) * 25 / 4;
    const int ty = tid >> 4, tx = tid & 15;
    const float* __restrict__ Ms = g_M[src][0];
    const int PS = MS * CW;
    ull acc[4][2];
#pragma unroll
    for (int i = 0; i < 4; i++) { acc[i][0] = 0ull; acc[i][1] = 0ull; }

    for (int kt = kt0; kt < kt1; ++kt) {
        const int k0 = kt * 16;
#pragma unroll
        for (int i = 0; i < 2; i++) {
            int idx = tid + i * 128;
            int r = idx >> 2, q = idx & 3;
            int rr = m0 + r; if (rr > MS - 1) rr = MS - 1;
            float4 v;
            if (first) {
                v = *reinterpret_cast<const float4*>(g_Bb + (size_t)rr * MS + k0 + q * 4);
            } else {
                const float* base = Ms + (size_t)rr * CW + k0 + q * 4;
                float4 v0 = *(const float4*)(base);
                float4 v1 = *(const float4*)(base + PS);
                float4 v2 = *(const float4*)(base + 2 * PS);
                float4 v3 = *(const float4*)(base + 3 * PS);
                v = make_float4(v0.x + v1.x + v2.x + v3.x, v0.y + v1.y + v2.y + v3.y,
                                v0.z + v1.z + v2.z + v3.z, v0.w + v1.w + v2.w + v3.w);
            }
            As[q * 4 + 0][r] = v.x; As[q * 4 + 1][r] = v.y;
            As[q * 4 + 2][r] = v.z; As[q * 4 + 3][r] = v.w;
        }
        {
            int kk = tid >> 3, c4 = tid & 7;
            int c = n0 + c4 * 4;
            int kr = k0 + kk;
            float4 v;
            if (first) {
                if (c < MS) v = *reinterpret_cast<const float4*>(g_Bb + (size_t)kr * MS + c);
                else        v = *reinterpret_cast<const float4*>(g_Xa + (size_t)kr * NRHS + (c - MS));
            } else {
                const float* base = Ms + (size_t)kr * CW + c;
                float4 v0 = *(const float4*)(base);
                float4 v1 = *(const float4*)(base + PS);
                float4 v2 = *(const float4*)(base + 2 * PS);
                float4 v3 = *(const float4*)(base + 3 * PS);
                v = make_float4(v0.x + v1.x + v2.x + v3.x, v0.y + v1.y + v2.y + v3.y,
                                v0.z + v1.z + v2.z + v3.z, v0.w + v1.w + v2.w + v3.w);
            }
            *reinterpret_cast<float4*>(&Bs2[kk][c4 * 8]) = make_float4(v.x, v.x, v.y, v.y);
            *reinterpret_cast<float4*>(&Bs2[kk][c4 * 8 + 4]) = make_float4(v.z, v.z, v.w, v.w);
        }
        __syncthreads();
#pragma unroll
        for (int k = 0; k < 16; k++) {
            float4 a0 = *(const float4*)&As[k][ty * 8];
            float4 a1 = *(const float4*)&As[k][ty * 8 + 4];
            float4 bq = *(const float4*)&Bs2[k][tx * 4];
            ull ap[4] = { pack2(a0.x, a0.y), pack2(a0.z, a0.w),
                          pack2(a1.x, a1.y), pack2(a1.z, a1.w) };
            ull b0 = pack2(bq.x, bq.y), b1 = pack2(bq.z, bq.w);
#pragma unroll
            for (int i = 0; i < 4; i++) {
                acc[i][0] = ffma2(ap[i], b0, acc[i][0]);
                acc[i][1] = ffma2(ap[i], b1, acc[i][1]);
            }
        }
        __syncthreads();
    }
    float* __restrict__ outp = g_M[dst][sp];
    int c = n0 + tx * 2;
#pragma unroll
    for (int i = 0; i < 4; i++) {
        int r0 = m0 + ty * 8 + 2 * i;
        if (r0 < MS) {
            float2 f0 = u2f(acc[i][0]);
            float2 f1 = u2f(acc[i][1]);
            float x00 = f0.x, x10 = f0.y, x01 = f1.x, x11 = f1.y;
            if (sp == 0 && c >= MS) {
                if (first) {
                    x00 += g_Xa[r0 * NRHS + (c - MS)];
                    x01 += g_Xa[r0 * NRHS + (c - MS) + 1];
                    x10 += g_Xa[(r0 + 1) * NRHS + (c - MS)];
                    x11 += g_Xa[(r0 + 1) * NRHS + (c - MS) + 1];
                } else {
                    const float* b0p = Ms + (size_t)r0 * CW + c;
                    const float* b1p = Ms + (size_t)(r0 + 1) * CW + c;
#pragma unroll
                    for (int p = 0; p < 4; p++) {
                        x00 += b0p[p * PS]; x01 += b0p[p * PS + 1];
                        x10 += b1p[p * PS]; x11 += b1p[p * PS + 1];
                    }
                }
            }
            *reinterpret_cast<ull*>(outp + (size_t)r0 * CW + c) = pack2(x00, x01);
            *reinterpret_cast<ull*>(outp + (size_t)(r0 + 1) * CW + c) = pack2(x10, x11);
        }
    }
}

// Materialize dense B^256 (-> g_Ba) and dense X (-> g_Xb) from buf-1 partials
__global__ void k_sumXB() {
    int i = blockIdx.x * 256 + threadIdx.x;
    if (i >= MS * CW) return;
    const int PS = MS * CW;
    const float* Ms = g_M[1][0];
    float s = Ms[i] + Ms[i + PS] + Ms[i + 2 * PS] + Ms[i + 3 * PS];
    int r = i / CW, c = i - r * CW;
    if (c < MS) g_Ba[(size_t)r * MS + c] = s;
    else g_Xb[r * NRHS + (c - MS)] = s;
}

// Final factor: Xa = Xb + B^last @ Xb
__global__ void k_xonly() {
    int idx = blockIdx.x * blockDim.x + threadIdx.x;
    if (idx >= MS * NRHS) return;
    int j = idx >> 4, c = idx & 15;
    const float* br = g_Ba + (size_t)j * MS;
    float s = g_Xb[idx];
#pragma unroll 4
    for (int k = 0; k < MS; k++) s = fmaf(br[k], g_Xb[k * NRHS + c], s);
    g_Xa[idx] = s;
}

// w[c][d] = omega * sum_j Xa[j][c] * K[j][d]
__global__ void k_w() {
    int idx = blockIdx.x * 256 + threadIdx.x;
    if (idx >= NRHS * DF) return;
    int c = idx / DF, d = idx - c * DF;
    float s = 0.f;
#pragma unroll 4
    for (int j = 0; j < MS; j++) s = fmaf(g_Xa[j * NRHS + c], g_KF[(size_t)j * DF + d], s);
    g_w[idx] = s * g_scal[1];
}

// Tt[c][r] = sum_d W[r][d] * w[c][d]   (r < 3072, c < 16)
__global__ void k_wT(const float* __restrict__ W) {
    int tid = threadIdx.x;
    int r = blockIdx.x * 16 + (tid >> 4);
    int c = tid & 15;
    const float4* wr = reinterpret_cast<const float4*>(W + (size_t)r * DF);
    const float4* wc = reinterpret_cast<const float4*>(g_w + (size_t)c * DF);
    float s = 0.f;
#pragma unroll 4
    for (int d = 0; d < DF / 4; d++) {
        float4 a = wr[d], b = wc[d];
        s = fmaf(a.x, b.x, s); s = fmaf(a.y, b.y, s);
        s = fmaf(a.z, b.z, s); s = fmaf(a.w, b.w, s);
    }
    g_Tt[c * CWH + r] = s;
}

// logits[q][c] = -gamma * sum_d Q_flat[q][d] * Tt[c][d]   (warp per output)
__global__ void k_out(float* __restrict__ out, const float* __restrict__ Qm,
                      const float* __restrict__ gamma) {
    int w = (blockIdx.x * blockDim.x + threadIdx.x) >> 5;
    int lane = threadIdx.x & 31;
    if (w >= MQ * NRHS) return;
    int q = w >> 4, c = w & 15;
    const float4* Qp = reinterpret_cast<const float4*>(Qm + (size_t)q * CWH);
    const float4* Tp = reinterpret_cast<const float4*>(g_Tt + (size_t)c * CWH);
    float s = 0.f;
    for (int i = lane; i < CWH / 4; i += 32) {
        float4 a = Qp[i], b = Tp[i];
        s = fmaf(a.x, b.x, s); s = fmaf(a.y, b.y, s);
        s = fmaf(a.z, b.z, s); s = fmaf(a.w, b.w, s);
    }
#pragma unroll
    for (int o = 16; o > 0; o >>= 1) s += __shfl_down_sync(0xffffffffu, s, o);
    if (lane == 0) out[w] = -gamma[0] * s;
}

// ============================================================
extern "C" void kernel_launch(void* const* d_in, const int* in_sizes, int n_in,
                              void* d_out, int out_size) {
    const float* S = (const float*)d_in[0];
    const float* Qm = (const float*)d_in[1];
    const float* W = (const float*)d_in[2];
    const float* gamma = (const float*)d_in[3];
    float* out = (float*)d_out;
    (void)in_sizes; (void)n_in; (void)out_size;

    k_gemm_kf<<<dim3(10, 7, SPLITS_KF), 128>>>(S, W);
    k_reduce_kf<<<(MS * DF + 255) / 256, 256>>>();
    k_gemm_aul<<<dim3(13, 7, 4), 128>>>();
    k_gemm_a2<<<dim3(13, 7, 4), 128>>>();
    k_fro<<<NRED, 256>>>();
    k_buildBX<<<(MS * MS + MS * NRHS + 255) / 256, 256>>>();
    k_iter<<<dim3(13, 7, 4), 128>>>(1, 0, 0);
    int src = 0, dst = 1;
    for (int j = 2; j <= 8; j++) {
        k_iter<<<dim3(13, 7, 4), 128>>>(0, src, dst);
        int t = src; src = dst; dst = t;
    }
    k_sumXB<<<(MS * CW + 255) / 256, 256>>>();
    k_xonly<<<(MS * NRHS + 255) / 256, 256>>>();
    k_w<<<(NRHS * DF + 255) / 256, 256>>>();
    k_wT<<<CWH / 16, 256>>>(W);
    k_out<<<(MQ * NRHS * 32 + 127) / 128, 128>>>(out, Qm, gamma);
}

// round 10
// speedup vs baseline: 1.1036x; 1.1036x over previous
#include <cuda_runtime.h>

typedef unsigned long long ull;

#define NSUP 25
#define CWH  3072
#define DF   640
#define MS   400
#define MQ   240
#define MKF  640
#define NRHS 16
#define CW   416
#define SPLITS_KF 8
#define NRED 625

// ---------------- device scratch ----------------
__device__ __align__(16) float g_KF[MKF * DF];                 // rows 0..399 = K, 400..639 = f_x
__device__ __align__(16) float g_parts[SPLITS_KF * MKF * DF];  // kf partials, then aul partials
__device__ __align__(16) float g_aul[MS * MS];
__device__ __align__(16) float g_A2[MS * MS];
__device__ __align__(16) float g_Ba[MS * MS];
__device__ __align__(16) float g_Bb[MS * MS];
__device__ __align__(16) float g_Xa[MS * NRHS];
__device__ __align__(16) float g_Xb[MS * NRHS];
__device__ __align__(16) float g_M[2][4][MS * CW];
__device__ float g_red[1024];
__device__ float g_scal[4];
__device__ __align__(16) float g_w[NRHS * DF];

// ---------------- packed f32x2 helpers ----------------
__device__ __forceinline__ ull ffma2(ull a, ull b, ull c) {
    ull d;
    asm("fma.rn.f32x2 %0, %1, %2, %3;" : "=l"(d) : "l"(a), "l"(b), "l"(c));
    return d;
}
union UF2 { float2 f; ull u; };
__device__ __forceinline__ ull pack2(float x, float y) {
    UF2 t; t.f = make_float2(x, y); return t.u;
}
__device__ __forceinline__ float2 u2f(ull v) { UF2 t; t.u = v; return t.f; }

// ============================================================
// GEMM KF: [S;Q](640x3072) @ W(3072x640), BM=128 BN=64 BK=16
// grid (10, 5, 8), 128 thr, 8x8 micro (f32x2), double-buffered
// ============================================================
__global__ __launch_bounds__(128) void k_gemm_kf(const float* __restrict__ S,
                                                 const float* __restrict__ Qm,
                                                 const float* __restrict__ W) {
    __shared__ float As[2][16][132];
    __shared__ float Bs[2][16][68];
    const int tid = threadIdx.x;
    const int n0 = blockIdx.x * 64;
    const int m0 = blockIdx.y * 128;
    const int sp = blockIdx.z;
    const int kt0 = sp * 24, kt1 = kt0 + 24;   // 192 kts / 8
    const int arow = m0 + tid;
    const float* Ap = (arow < MS) ? (S + (size_t)arow * CWH)
                                  : (Qm + (size_t)(arow - MS) * CWH);
    const int ty = tid >> 3, tx = tid & 7;
    ull acc[8][4];
#pragma unroll
    for (int i = 0; i < 8; i++)
#pragma unroll
        for (int u = 0; u < 4; u++) acc[i][u] = 0ull;

    float4 pa[4], pb[2];
    {
        const int k0 = kt0 * 16;
#pragma unroll
        for (int q = 0; q < 4; q++) pa[q] = *reinterpret_cast<const float4*>(Ap + k0 + q * 4);
#pragma unroll
        for (int i = 0; i < 2; i++) {
            int idx = tid + i * 128;
            int kk = idx >> 4, c4 = idx & 15;
            pb[i] = *reinterpret_cast<const float4*>(W + (size_t)(k0 + kk) * DF + n0 + c4 * 4);
        }
    }
    int cur = 0;
#pragma unroll
    for (int q = 0; q < 4; q++) {
        As[0][q * 4 + 0][tid] = pa[q].x; As[0][q * 4 + 1][tid] = pa[q].y;
        As[0][q * 4 + 2][tid] = pa[q].z; As[0][q * 4 + 3][tid] = pa[q].w;
    }
#pragma unroll
    for (int i = 0; i < 2; i++) {
        int idx = tid + i * 128;
        int kk = idx >> 4, c4 = idx & 15;
        *reinterpret_cast<float4*>(&Bs[0][kk][c4 * 4]) = pb[i];
    }
    __syncthreads();

    for (int kt = kt0; kt < kt1; ++kt) {
        const bool hn = (kt + 1 < kt1);
        if (hn) {
            const int k0 = (kt + 1) * 16;
#pragma unroll
            for (int q = 0; q < 4; q++) pa[q] = *reinterpret_cast<const float4*>(Ap + k0 + q * 4);
#pragma unroll
            for (int i = 0; i < 2; i++) {
                int idx = tid + i * 128;
                int kk = idx >> 4, c4 = idx & 15;
                pb[i] = *reinterpret_cast<const float4*>(W + (size_t)(k0 + kk) * DF + n0 + c4 * 4);
            }
        }
        const float (*Ac)[132] = As[cur];
        const float (*Bc)[68] = Bs[cur];
#pragma unroll
        for (int k = 0; k < 16; k++) {
            float av[8];
            *(float4*)&av[0] = *(const float4*)&Ac[k][ty * 8];
            *(float4*)&av[4] = *(const float4*)&Ac[k][ty * 8 + 4];
            ull bv[4];
#pragma unroll
            for (int u = 0; u < 4; u++)
                bv[u] = *reinterpret_cast<const ull*>(&Bc[k][tx * 8 + 2 * u]);
#pragma unroll
            for (int i = 0; i < 8; i++) {
                ull ai = pack2(av[i], av[i]);
#pragma unroll
                for (int u = 0; u < 4; u++) acc[i][u] = ffma2(ai, bv[u], acc[i][u]);
            }
        }
        if (hn) {
            int nb = cur ^ 1;
#pragma unroll
            for (int q = 0; q < 4; q++) {
                As[nb][q * 4 + 0][tid] = pa[q].x; As[nb][q * 4 + 1][tid] = pa[q].y;
                As[nb][q * 4 + 2][tid] = pa[q].z; As[nb][q * 4 + 3][tid] = pa[q].w;
            }
#pragma unroll
            for (int i = 0; i < 2; i++) {
                int idx = tid + i * 128;
                int kk = idx >> 4, c4 = idx & 15;
                *reinterpret_cast<float4*>(&Bs[nb][kk][c4 * 4]) = pb[i];
            }
            __syncthreads();
            cur = nb;
        }
    }
    float* out = g_parts + (size_t)sp * MKF * DF;
#pragma unroll
    for (int i = 0; i < 8; i++) {
        int r = m0 + ty * 8 + i;
#pragma unroll
        for (int u = 0; u < 4; u++)
            *reinterpret_cast<ull*>(out + (size_t)r * DF + n0 + tx * 8 + 2 * u) = acc[i][u];
    }
}

__global__ void k_reduce_kf() {
    int i = blockIdx.x * 256 + threadIdx.x;
    if (i >= MKF * DF) return;
    const size_t T = (size_t)MKF * DF;
    float s = 0.f;
#pragma unroll
    for (int p = 0; p < SPLITS_KF; p++) s += g_parts[p * T + i];
    g_KF[i] = s;
}

// ============================================================
// aul = K K^T (NT, 400x400x640) split-K=4 -> partials, double-buffered
// grid (13,7,4), BM=64 BN=32
// ============================================================
__global__ __launch_bounds__(128) void k_gemm_aul() {
    __shared__ float As[2][16][68];
    __shared__ float Bs2[2][16][72];
    const int tid = threadIdx.x;
    const int n0 = blockIdx.x * 32;
    const int m0 = blockIdx.y * 64;
    const int sp = blockIdx.z;
    const int kt0 = sp * 10, kt1 = kt0 + 10;
    const int ty = tid >> 4, tx = tid & 15;
    const int ar = tid >> 2, aq = tid & 3;     // A loader (two rows: ar, ar+32)
    int rr0 = m0 + ar; if (rr0 > MS - 1) rr0 = MS - 1;
    int rr1 = m0 + ar + 32; if (rr1 > MS - 1) rr1 = MS - 1;
    int nn = n0 + ar; if (nn > MS - 1) nn = MS - 1;   // B loader row
    ull acc[4][2];
#pragma unroll
    for (int i = 0; i < 4; i++) { acc[i][0] = 0ull; acc[i][1] = 0ull; }

    float4 pa0, pa1, pb;
    {
        const int k0 = kt0 * 16;
        pa0 = *reinterpret_cast<const float4*>(g_KF + (size_t)rr0 * DF + k0 + aq * 4);
        pa1 = *reinterpret_cast<const float4*>(g_KF + (size_t)rr1 * DF + k0 + aq * 4);
        pb  = *reinterpret_cast<const float4*>(g_KF + (size_t)nn * DF + k0 + aq * 4);
    }
    int cur = 0;
    {
        As[0][aq * 4 + 0][ar] = pa0.x; As[0][aq * 4 + 1][ar] = pa0.y;
        As[0][aq * 4 + 2][ar] = pa0.z; As[0][aq * 4 + 3][ar] = pa0.w;
        As[0][aq * 4 + 0][ar + 32] = pa1.x; As[0][aq * 4 + 1][ar + 32] = pa1.y;
        As[0][aq * 4 + 2][ar + 32] = pa1.z; As[0][aq * 4 + 3][ar + 32] = pa1.w;
        *reinterpret_cast<ull*>(&Bs2[0][aq * 4 + 0][ar * 2]) = pack2(pb.x, pb.x);
        *reinterpret_cast<ull*>(&Bs2[0][aq * 4 + 1][ar * 2]) = pack2(pb.y, pb.y);
        *reinterpret_cast<ull*>(&Bs2[0][aq * 4 + 2][ar * 2]) = pack2(pb.z, pb.z);
        *reinterpret_cast<ull*>(&Bs2[0][aq * 4 + 3][ar * 2]) = pack2(pb.w, pb.w);
    }
    __syncthreads();

    for (int kt = kt0; kt < kt1; ++kt) {
        const bool hn = (kt + 1 < kt1);
        if (hn) {
            const int k0 = (kt + 1) * 16;
            pa0 = *reinterpret_cast<const float4*>(g_KF + (size_t)rr0 * DF + k0 + aq * 4);
            pa1 = *reinterpret_cast<const float4*>(g_KF + (size_t)rr1 * DF + k0 + aq * 4);
            pb  = *reinterpret_cast<const float4*>(g_KF + (size_t)nn * DF + k0 + aq * 4);
        }
        const float (*Ac)[68] = As[cur];
        const float (*Bc)[72] = Bs2[cur];
#pragma unroll
        for (int k = 0; k < 16; k++) {
            float4 a0 = *(const float4*)&Ac[k][ty * 8];
            float4 a1 = *(const float4*)&Ac[k][ty * 8 + 4];
            float4 bq = *(const float4*)&Bc[k][tx * 4];
            ull ap[4] = { pack2(a0.x, a0.y), pack2(a0.z, a0.w),
                          pack2(a1.x, a1.y), pack2(a1.z, a1.w) };
            ull b0 = pack2(bq.x, bq.y), b1 = pack2(bq.z, bq.w);
#pragma unroll
            for (int i = 0; i < 4; i++) {
                acc[i][0] = ffma2(ap[i], b0, acc[i][0]);
                acc[i][1] = ffma2(ap[i], b1, acc[i][1]);
            }
        }
        if (hn) {
            int nb = cur ^ 1;
            As[nb][aq * 4 + 0][ar] = pa0.x; As[nb][aq * 4 + 1][ar] = pa0.y;
            As[nb][aq * 4 + 2][ar] = pa0.z; As[nb][aq * 4 + 3][ar] = pa0.w;
            As[nb][aq * 4 + 0][ar + 32] = pa1.x; As[nb][aq * 4 + 1][ar + 32] = pa1.y;
            As[nb][aq * 4 + 2][ar + 32] = pa1.z; As[nb][aq * 4 + 3][ar + 32] = pa1.w;
            *reinterpret_cast<ull*>(&Bs2[nb][aq * 4 + 0][ar * 2]) = pack2(pb.x, pb.x);
            *reinterpret_cast<ull*>(&Bs2[nb][aq * 4 + 1][ar * 2]) = pack2(pb.y, pb.y);
            *reinterpret_cast<ull*>(&Bs2[nb][aq * 4 + 2][ar * 2]) = pack2(pb.z, pb.z);
            *reinterpret_cast<ull*>(&Bs2[nb][aq * 4 + 3][ar * 2]) = pack2(pb.w, pb.w);
            __syncthreads();
            cur = nb;
        }
    }
    float* out = g_parts + (size_t)sp * MS * MS;
    int c = n0 + tx * 2;
    if (c < MS) {
#pragma unroll
        for (int i = 0; i < 4; i++) {
            int r0 = m0 + ty * 8 + 2 * i;
            if (r0 < MS) {
                float2 f0 = u2f(acc[i][0]);
                float2 f1 = u2f(acc[i][1]);
                *reinterpret_cast<ull*>(out + (size_t)r0 * MS + c) = pack2(f0.x, f1.x);
                *reinterpret_cast<ull*>(out + (size_t)(r0 + 1) * MS + c) = pack2(f0.y, f1.y);
            }
        }
    }
}

__global__ void k_red_aul() {
    int i = blockIdx.x * 256 + threadIdx.x;
    if (i >= MS * MS) return;
    const size_t T = (size_t)MS * MS;
    float s = g_parts[i] + g_parts[T + i] + g_parts[2 * T + i] + g_parts[3 * T + i];
    int r = i / MS, c = i - r * MS;
    if (r == c) s += 50.0f;
    g_aul[i] = s;
}

// ============================================================
// A2 = aul @ aul (NN), split-K=4 -> partials in g_M[0], double-buffered
// ============================================================
__global__ __launch_bounds__(128) void k_gemm_a2() {
    __shared__ float As[2][16][68];
    __shared__ float Bs2[2][16][72];
    const int tid = threadIdx.x;
    const int n0 = blockIdx.x * 32;
    const int m0 = blockIdx.y * 64;
    const int sp = blockIdx.z;
    const int kt0 = sp * 25 / 4, kt1 = (sp + 1) * 25 / 4;
    const int ty = tid >> 4, tx = tid & 15;
    const int ar = tid >> 2, aq = tid & 3;
    int rr0 = m0 + ar; if (rr0 > MS - 1) rr0 = MS - 1;
    int rr1 = m0 + ar + 32; if (rr1 > MS - 1) rr1 = MS - 1;
    const int bkk = tid >> 3, bc4 = tid & 7;
    const int bc = n0 + bc4 * 4;
    ull acc[4][2];
#pragma unroll
    for (int i = 0; i < 4; i++) { acc[i][0] = 0ull; acc[i][1] = 0ull; }

    float4 pa0, pa1, pb;
    {
        const int k0 = kt0 * 16;
        pa0 = *reinterpret_cast<const float4*>(g_aul + (size_t)rr0 * MS + k0 + aq * 4);
        pa1 = *reinterpret_cast<const float4*>(g_aul + (size_t)rr1 * MS + k0 + aq * 4);
        pb = make_float4(0.f, 0.f, 0.f, 0.f);
        if (bc < MS) pb = *reinterpret_cast<const float4*>(g_aul + (size_t)(k0 + bkk) * MS + bc);
    }
    int cur = 0;
    {
        As[0][aq * 4 + 0][ar] = pa0.x; As[0][aq * 4 + 1][ar] = pa0.y;
        As[0][aq * 4 + 2][ar] = pa0.z; As[0][aq * 4 + 3][ar] = pa0.w;
        As[0][aq * 4 + 0][ar + 32] = pa1.x; As[0][aq * 4 + 1][ar + 32] = pa1.y;
        As[0][aq * 4 + 2][ar + 32] = pa1.z; As[0][aq * 4 + 3][ar + 32] = pa1.w;
        *reinterpret_cast<float4*>(&Bs2[0][bkk][bc4 * 8]) = make_float4(pb.x, pb.x, pb.y, pb.y);
        *reinterpret_cast<float4*>(&Bs2[0][bkk][bc4 * 8 + 4]) = make_float4(pb.z, pb.z, pb.w, pb.w);
    }
    __syncthreads();

    for (int kt = kt0; kt < kt1; ++kt) {
        const bool hn = (kt + 1 < kt1);
        if (hn) {
            const int k0 = (kt + 1) * 16;
            pa0 = *reinterpret_cast<const float4*>(g_aul + (size_t)rr0 * MS + k0 + aq * 4);
            pa1 = *reinterpret_cast<const float4*>(g_aul + (size_t)rr1 * MS + k0 + aq * 4);
            pb = make_float4(0.f, 0.f, 0.f, 0.f);
            if (bc < MS) pb = *reinterpret_cast<const float4*>(g_aul + (size_t)(k0 + bkk) * MS + bc);
        }
        const float (*Ac)[68] = As[cur];
        const float (*Bc)[72] = Bs2[cur];
#pragma unroll
        for (int k = 0; k < 16; k++) {
            float4 a0 = *(const float4*)&Ac[k][ty * 8];
            float4 a1 = *(const float4*)&Ac[k][ty * 8 + 4];
            float4 bq = *(const float4*)&Bc[k][tx * 4];
            ull ap[4] = { pack2(a0.x, a0.y), pack2(a0.z, a0.w),
                          pack2(a1.x, a1.y), pack2(a1.z, a1.w) };
            ull b0 = pack2(bq.x, bq.y), b1 = pack2(bq.z, bq.w);
#pragma unroll
            for (int i = 0; i < 4; i++) {
                acc[i][0] = ffma2(ap[i], b0, acc[i][0]);
                acc[i][1] = ffma2(ap[i], b1, acc[i][1]);
            }
        }
        if (hn) {
            int nb = cur ^ 1;
            As[nb][aq * 4 + 0][ar] = pa0.x; As[nb][aq * 4 + 1][ar] = pa0.y;
            As[nb][aq * 4 + 2][ar] = pa0.z; As[nb][aq * 4 + 3][ar] = pa0.w;
            As[nb][aq * 4 + 0][ar + 32] = pa1.x; As[nb][aq * 4 + 1][ar + 32] = pa1.y;
            As[nb][aq * 4 + 2][ar + 32] = pa1.z; As[nb][aq * 4 + 3][ar + 32] = pa1.w;
            *reinterpret_cast<float4*>(&Bs2[nb][bkk][bc4 * 8]) = make_float4(pb.x, pb.x, pb.y, pb.y);
            *reinterpret_cast<float4*>(&Bs2[nb][bkk][bc4 * 8 + 4]) = make_float4(pb.z, pb.z, pb.w, pb.w);
            __syncthreads();
            cur = nb;
        }
    }
    float* out = g_M[0][sp];
    int c = n0 + tx * 2;
    if (c < MS) {
#pragma unroll
        for (int i = 0; i < 4; i++) {
            int r0 = m0 + ty * 8 + 2 * i;
            if (r0 < MS) {
                float2 f0 = u2f(acc[i][0]);
                float2 f1 = u2f(acc[i][1]);
                *reinterpret_cast<ull*>(out + (size_t)r0 * MS + c) = pack2(f0.x, f1.x);
                *reinterpret_cast<ull*>(out + (size_t)(r0 + 1) * MS + c) = pack2(f0.y, f1.y);
            }
        }
    }
}

// Sum A2 partials -> g_A2 + Frobenius^2 block partials
__global__ void k_fro() {
    int i = blockIdx.x * 256 + threadIdx.x;
    float v = 0.f;
    if (i < MS * MS) {
        v = g_M[0][0][i] + g_M[0][1][i] + g_M[0][2][i] + g_M[0][3][i];
        g_A2[i] = v;
    }
    __shared__ float sh[256];
    sh[threadIdx.x] = v * v; __syncthreads();
    for (int o = 128; o > 0; o >>= 1) {
        if (threadIdx.x < o) sh[threadIdx.x] += sh[threadIdx.x + o];
        __syncthreads();
    }
    if (threadIdx.x == 0) g_red[blockIdx.x] = sh[0];
}

// omega = 2/(b+50); B^2 = I - 2wA + w^2 A2 ; X1 = 2P - w*rowblocksum(aul)
__global__ void k_buildBX() {
    __shared__ float sh[256];
    float t = 0.f;
    for (int i = threadIdx.x; i < NRED; i += 256) t += g_red[i];
    sh[threadIdx.x] = t; __syncthreads();
    for (int o = 128; o > 0; o >>= 1) {
        if (threadIdx.x < o) sh[threadIdx.x] += sh[threadIdx.x + o];
        __syncthreads();
    }
    float b = sqrtf(sqrtf(sh[0])) * 1.0001f;
    if (!(b > 51.f)) b = 51.f;
    float om = 2.0f / (b + 50.0f);
    if (blockIdx.x == 0 && threadIdx.x == 0) g_scal[1] = om;

    int i = blockIdx.x * 256 + threadIdx.x;
    if (i < MS * MS) {
        int r = i / MS, c = i - r * MS;
        float a = g_aul[i] * om;
        float a2 = g_A2[i] * om * om;
        float d = (r == c) ? 1.f : 0.f;
        g_Bb[i] = d - 2.f * a + a2;
    } else if (i < MS * MS + MS * NRHS) {
        int idx = i - MS * MS;
        int j = idx >> 4, c = idx & 15;
        float s = ((j / NSUP) == c) ? 2.f : 0.f;
        const float* row = g_aul + (size_t)j * MS + c * NSUP;
        float u = 0.f;
#pragma unroll
        for (int q = 0; q < NSUP; q++) u += row[q];
        g_Xa[idx] = s - u * om;
    }
}

// ============================================================
// Chain iteration, split-K=4, partial in / out, double-buffered
// ============================================================
__global__ __launch_bounds__(128) void k_iter(int first, int src, int dst) {
    __shared__ float As[2][16][68];
    __shared__ float Bs2[2][16][72];
    const int tid = threadIdx.x;
    const int n0 = blockIdx.x * 32;
    const int m0 = blockIdx.y * 64;
    const int sp = blockIdx.z;
    const int kt0 = sp * 25 / 4, kt1 = (sp + 1) * 25 / 4;
    const int ty = tid >> 4, tx = tid & 15;
    const float* __restrict__ Ms = g_M[src][0];
    const int PS = MS * CW;
    const int ar = tid >> 2, aq = tid & 3;
    int rr0 = m0 + ar; if (rr0 > MS - 1) rr0 = MS - 1;
    int rr1 = m0 + ar + 32; if (rr1 > MS - 1) rr1 = MS - 1;
    const int bkk = tid >> 3, bc4 = tid & 7;
    const int bc = n0 + bc4 * 4;
    ull acc[4][2];
#pragma unroll
    for (int i = 0; i < 4; i++) { acc[i][0] = 0ull; acc[i][1] = 0ull; }

    float4 pa0, pa1, pb;
    // prefetch lambda-free loaders
#define LOAD_A(dst4, rr, kt_)  do {                                             \
        const int k0_ = (kt_) * 16;                                             \
        if (first) {                                                            \
            dst4 = *reinterpret_cast<const float4*>(g_Bb + (size_t)(rr) * MS + k0_ + aq * 4); \
        } else {                                                                \
            const float* base = Ms + (size_t)(rr) * CW + k0_ + aq * 4;          \
            float4 v0 = *(const float4*)(base);                                 \
            float4 v1 = *(const float4*)(base + PS);                            \
            float4 v2 = *(const float4*)(base + 2 * PS);                        \
            float4 v3 = *(const float4*)(base + 3 * PS);                        \
            dst4 = make_float4(v0.x + v1.x + v2.x + v3.x, v0.y + v1.y + v2.y + v3.y, \
                               v0.z + v1.z + v2.z + v3.z, v0.w + v1.w + v2.w + v3.w); \
        }                                                                       \
    } while (0)
#define LOAD_B(dst4, kt_)  do {                                                 \
        const int kr_ = (kt_) * 16 + bkk;                                       \
        if (first) {                                                            \
            if (bc < MS) dst4 = *reinterpret_cast<const float4*>(g_Bb + (size_t)kr_ * MS + bc); \
            else         dst4 = *reinterpret_cast<const float4*>(g_Xa + (size_t)kr_ * NRHS + (bc - MS)); \
        } else {                                                                \
            const float* base = Ms + (size_t)kr_ * CW + bc;                     \
            float4 v0 = *(const float4*)(base);                                 \
            float4 v1 = *(const float4*)(base + PS);                            \
            float4 v2 = *(const float4*)(base + 2 * PS);                        \
            float4 v3 = *(const float4*)(base + 3 * PS);                        \
            dst4 = make_float4(v0.x + v1.x + v2.x + v3.x, v0.y + v1.y + v2.y + v3.y, \
                               v0.z + v1.z + v2.z + v3.z, v0.w + v1.w + v2.w + v3.w); \
        }                                                                       \
    } while (0)

    LOAD_A(pa0, rr0, kt0);
    LOAD_A(pa1, rr1, kt0);
    LOAD_B(pb, kt0);
    int cur = 0;
    {
        As[0][aq * 4 + 0][ar] = pa0.x; As[0][aq * 4 + 1][ar] = pa0.y;
        As[0][aq * 4 + 2][ar] = pa0.z; As[0][aq * 4 + 3][ar] = pa0.w;
        As[0][aq * 4 + 0][ar + 32] = pa1.x; As[0][aq * 4 + 1][ar + 32] = pa1.y;
        As[0][aq * 4 + 2][ar + 32] = pa1.z; As[0][aq * 4 + 3][ar + 32] = pa1.w;
        *reinterpret_cast<float4*>(&Bs2[0][bkk][bc4 * 8]) = make_float4(pb.x, pb.x, pb.y, pb.y);
        *reinterpret_cast<float4*>(&Bs2[0][bkk][bc4 * 8 + 4]) = make_float4(pb.z, pb.z, pb.w, pb.w);
    }
    __syncthreads();

    for (int kt = kt0; kt < kt1; ++kt) {
        const bool hn = (kt + 1 < kt1);
        if (hn) {
            LOAD_A(pa0, rr0, kt + 1);
            LOAD_A(pa1, rr1, kt + 1);
            LOAD_B(pb, kt + 1);
        }
        const float (*Ac)[68] = As[cur];
        const float (*Bc)[72] = Bs2[cur];
#pragma unroll
        for (int k = 0; k < 16; k++) {
            float4 a0 = *(const float4*)&Ac[k][ty * 8];
            float4 a1 = *(const float4*)&Ac[k][ty * 8 + 4];
            float4 bq = *(const float4*)&Bc[k][tx * 4];
            ull ap[4] = { pack2(a0.x, a0.y), pack2(a0.z, a0.w),
                          pack2(a1.x, a1.y), pack2(a1.z, a1.w) };
            ull b0 = pack2(bq.x, bq.y), b1 = pack2(bq.z, bq.w);
#pragma unroll
            for (int i = 0; i < 4; i++) {
                acc[i][0] = ffma2(ap[i], b0, acc[i][0]);
                acc[i][1] = ffma2(ap[i], b1, acc[i][1]);
            }
        }
        if (hn) {
            int nb = cur ^ 1;
            As[nb][aq * 4 + 0][ar] = pa0.x; As[nb][aq * 4 + 1][ar] = pa0.y;
            As[nb][aq * 4 + 2][ar] = pa0.z; As[nb][aq * 4 + 3][ar] = pa0.w;
            As[nb][aq * 4 + 0][ar + 32] = pa1.x; As[nb][aq * 4 + 1][ar + 32] = pa1.y;
            As[nb][aq * 4 + 2][ar + 32] = pa1.z; As[nb][aq * 4 + 3][ar + 32] = pa1.w;
            *reinterpret_cast<float4*>(&Bs2[nb][bkk][bc4 * 8]) = make_float4(pb.x, pb.x, pb.y, pb.y);
            *reinterpret_cast<float4*>(&Bs2[nb][bkk][bc4 * 8 + 4]) = make_float4(pb.z, pb.z, pb.w, pb.w);
            __syncthreads();
            cur = nb;
        }
    }
#undef LOAD_A
#undef LOAD_B
    float* __restrict__ outp = g_M[dst][sp];
    int c = n0 + tx * 2;
#pragma unroll
    for (int i = 0; i < 4; i++) {
        int r0 = m0 + ty * 8 + 2 * i;
        if (r0 < MS) {
            float2 f0 = u2f(acc[i][0]);
            float2 f1 = u2f(acc[i][1]);
            float x00 = f0.x, x10 = f0.y, x01 = f1.x, x11 = f1.y;
            if (sp == 0 && c >= MS) {
                if (first) {
                    x00 += g_Xa[r0 * NRHS + (c - MS)];
                    x01 += g_Xa[r0 * NRHS + (c - MS) + 1];
                    x10 += g_Xa[(r0 + 1) * NRHS + (c - MS)];
                    x11 += g_Xa[(r0 + 1) * NRHS + (c - MS) + 1];
                } else {
                    const float* b0p = Ms + (size_t)r0 * CW + c;
                    const float* b1p = Ms + (size_t)(r0 + 1) * CW + c;
#pragma unroll
                    for (int p = 0; p < 4; p++) {
                        x00 += b0p[p * PS]; x01 += b0p[p * PS + 1];
                        x10 += b1p[p * PS]; x11 += b1p[p * PS + 1];
                    }
                }
            }
            *reinterpret_cast<ull*>(outp + (size_t)r0 * CW + c) = pack2(x00, x01);
            *reinterpret_cast<ull*>(outp + (size_t)(r0 + 1) * CW + c) = pack2(x10, x11);
        }
    }
}

// Materialize dense B^256 (-> g_Ba) and dense X (-> g_Xb) from buf-1 partials
__global__ void k_sumXB() {
    int i = blockIdx.x * 256 + threadIdx.x;
    if (i >= MS * CW) return;
    const int PS = MS * CW;
    const float* Ms = g_M[1][0];
    float s = Ms[i] + Ms[i + PS] + Ms[i + 2 * PS] + Ms[i + 3 * PS];
    int r = i / CW, c = i - r * CW;
    if (c < MS) g_Ba[(size_t)r * MS + c] = s;
    else g_Xb[r * NRHS + (c - MS)] = s;
}

// Final factor: Xa = Xb + B^last @ Xb
__global__ void k_xonly() {
    int idx = blockIdx.x * blockDim.x + threadIdx.x;
    if (idx >= MS * NRHS) return;
    int j = idx >> 4, c = idx & 15;
    const float* br = g_Ba + (size_t)j * MS;
    float s = g_Xb[idx];
#pragma unroll 4
    for (int k = 0; k < MS; k++) s = fmaf(br[k], g_Xb[k * NRHS + c], s);
    g_Xa[idx] = s;
}

// w[c][d] = omega * sum_j Xa[j][c] * K[j][d]
__global__ void k_w() {
    int idx = blockIdx.x * 256 + threadIdx.x;
    if (idx >= NRHS * DF) return;
    int c = idx / DF, d = idx - c * DF;
    float s = 0.f;
#pragma unroll 4
    for (int j = 0; j < MS; j++) s = fmaf(g_Xa[j * NRHS + c], g_KF[(size_t)j * DF + d], s);
    g_w[idx] = s * g_scal[1];
}

// logits[q][c] = -gamma * sum_d f_x[q][d] * w[c][d]
__global__ void k_logits(float* __restrict__ out, const float* __restrict__ gamma) {
    int idx = blockIdx.x * 256 + threadIdx.x;
    if (idx >= MQ * 16) return;
    int q = idx >> 4, c = idx & 15;
    const float4* f = reinterpret_cast<const float4*>(g_KF + (size_t)(MS + q) * DF);
    const float4* wr = reinterpret_cast<const float4*>(g_w + (size_t)c * DF);
    float s = 0.f;
#pragma unroll 4
    for (int d = 0; d < DF / 4; d++) {
        float4 a = f[d], b = wr[d];
        s = fmaf(a.x, b.x, s); s = fmaf(a.y, b.y, s);
        s = fmaf(a.z, b.z, s); s = fmaf(a.w, b.w, s);
    }
    out[idx] = -gamma[0] * s;
}

// ============================================================
extern "C" void kernel_launch(void* const* d_in, const int* in_sizes, int n_in,
                              void* d_out, int out_size) {
    const float* S = (const float*)d_in[0];
    const float* Qm = (const float*)d_in[1];
    const float* W = (const float*)d_in[2];
    const float* gamma = (const float*)d_in[3];
    float* out = (float*)d_out;
    (void)in_sizes; (void)n_in; (void)out_size;

    k_gemm_kf<<<dim3(10, 5, SPLITS_KF), 128>>>(S, Qm, W);
    k_reduce_kf<<<(MKF * DF + 255) / 256, 256>>>();
    k_gemm_aul<<<dim3(13, 7, 4), 128>>>();
    k_red_aul<<<(MS * MS + 255) / 256, 256>>>();
    k_gemm_a2<<<dim3(13, 7, 4), 128>>>();
    k_fro<<<NRED, 256>>>();
    k_buildBX<<<(MS * MS + MS * NRHS + 255) / 256, 256>>>();
    k_iter<<<dim3(13, 7, 4), 128>>>(1, 0, 0);
    int src = 0, dst = 1;
    for (int j = 2; j <= 8; j++) {
        k_iter<<<dim3(13, 7, 4), 128>>>(0, src, dst);
        int t = src; src = dst; dst = t;
    }
    k_sumXB<<<(MS * CW + 255) / 256, 256>>>();
    k_xonly<<<(MS * NRHS + 255) / 256, 256>>>();
    k_w<<<(NRHS * DF + 255) / 256, 256>>>();
    k_logits<<<(MQ * 16 + 255) / 256, 256>>>(out, gamma);
}

// round 11
// speedup vs baseline: 1.1866x; 1.0752x over previous
#include <cuda_runtime.h>

typedef unsigned long long ull;

#define NSUP 25
#define CWH  3072
#define DF   640
#define MS   400
#define MQ   240
#define MKF  640
#define NRHS 16
#define CW   416
#define SPLITS_KF 8
#define GRID_CH 364          // 13 x 7 x 4
#define NT_CH   (GRID_CH * 128)
#define NPH 15               // global barriers per chain launch

// ---------------- device scratch ----------------
__device__ __align__(16) float g_KF[MKF * DF];                 // rows 0..399 = K, 400..639 = f_x
__device__ __align__(16) float g_parts[SPLITS_KF * MKF * DF];  // kf partials, then aul partials
__device__ __align__(16) float g_aul[MS * MS];
__device__ __align__(16) float g_A2[MS * MS];
__device__ __align__(16) float g_Ba[MS * MS];
__device__ __align__(16) float g_Bb[MS * MS];
__device__ __align__(16) float g_Xa[MS * NRHS];
__device__ __align__(16) float g_Xb[MS * NRHS];
__device__ __align__(16) float g_M[2][4][MS * CW];
__device__ float g_red[512];
__device__ float g_scal[4];
__device__ __align__(16) float g_w[NRHS * DF];
__device__ unsigned g_bar[NPH];          // zero-initialized; cyclically reset

// ---------------- packed f32x2 helpers ----------------
__device__ __forceinline__ ull ffma2(ull a, ull b, ull c) {
    ull d;
    asm("fma.rn.f32x2 %0, %1, %2, %3;" : "=l"(d) : "l"(a), "l"(b), "l"(c));
    return d;
}
union UF2 { float2 f; ull u; };
__device__ __forceinline__ ull pack2(float x, float y) {
    UF2 t; t.f = make_float2(x, y); return t.u;
}
__device__ __forceinline__ float2 u2f(ull v) { UF2 t; t.u = v; return t.f; }

// ---------------- global software barrier ----------------
// Release-arrive + acquire-spin; counter (p+NPH-1)%NPH reset by the last
// arriver at p (safe: arriving at p implies having passed p-1). Counter 14
// is reset at barrier 0 of the NEXT launch, so replays start clean.
__device__ __forceinline__ void gbar(int p) {
    __syncthreads();
    if (threadIdx.x == 0) {
        unsigned old;
        asm volatile("atom.release.gpu.global.add.u32 %0, [%1], 1;"
                     : "=r"(old) : "l"(&g_bar[p]) : "memory");
        if (old == GRID_CH - 1) {
            unsigned zero = 0;
            asm volatile("st.relaxed.gpu.global.u32 [%0], %1;"
                         :: "l"(&g_bar[(p + NPH - 1) % NPH]), "r"(zero) : "memory");
        }
        unsigned v;
        do {
            asm volatile("ld.acquire.gpu.global.u32 %0, [%1];"
                         : "=r"(v) : "l"(&g_bar[p]) : "memory");
        } while (v < GRID_CH);
    }
    __syncthreads();
}

// ============================================================
// GEMM KF: [S;Q](640x3072) @ W(3072x640), BM=128 BN=64 BK=16
// grid (10, 5, 8), 128 thr, 8x8 micro (f32x2), double-buffered
// ============================================================
__global__ __launch_bounds__(128) void k_gemm_kf(const float* __restrict__ S,
                                                 const float* __restrict__ Qm,
                                                 const float* __restrict__ W) {
    __shared__ float As[2][16][132];
    __shared__ float Bs[2][16][68];
    const int tid = threadIdx.x;
    const int n0 = blockIdx.x * 64;
    const int m0 = blockIdx.y * 128;
    const int sp = blockIdx.z;
    const int kt0 = sp * 24, kt1 = kt0 + 24;
    const int arow = m0 + tid;
    const float* Ap = (arow < MS) ? (S + (size_t)arow * CWH)
                                  : (Qm + (size_t)(arow - MS) * CWH);
    const int ty = tid >> 3, tx = tid & 7;
    ull acc[8][4];
#pragma unroll
    for (int i = 0; i < 8; i++)
#pragma unroll
        for (int u = 0; u < 4; u++) acc[i][u] = 0ull;

    float4 pa[4], pb[2];
    {
        const int k0 = kt0 * 16;
#pragma unroll
        for (int q = 0; q < 4; q++) pa[q] = *reinterpret_cast<const float4*>(Ap + k0 + q * 4);
#pragma unroll
        for (int i = 0; i < 2; i++) {
            int idx = tid + i * 128;
            int kk = idx >> 4, c4 = idx & 15;
            pb[i] = *reinterpret_cast<const float4*>(W + (size_t)(k0 + kk) * DF + n0 + c4 * 4);
        }
    }
    int cur = 0;
#pragma unroll
    for (int q = 0; q < 4; q++) {
        As[0][q * 4 + 0][tid] = pa[q].x; As[0][q * 4 + 1][tid] = pa[q].y;
        As[0][q * 4 + 2][tid] = pa[q].z; As[0][q * 4 + 3][tid] = pa[q].w;
    }
#pragma unroll
    for (int i = 0; i < 2; i++) {
        int idx = tid + i * 128;
        int kk = idx >> 4, c4 = idx & 15;
        *reinterpret_cast<float4*>(&Bs[0][kk][c4 * 4]) = pb[i];
    }
    __syncthreads();

    for (int kt = kt0; kt < kt1; ++kt) {
        const bool hn = (kt + 1 < kt1);
        if (hn) {
            const int k0 = (kt + 1) * 16;
#pragma unroll
            for (int q = 0; q < 4; q++) pa[q] = *reinterpret_cast<const float4*>(Ap + k0 + q * 4);
#pragma unroll
            for (int i = 0; i < 2; i++) {
                int idx = tid + i * 128;
                int kk = idx >> 4, c4 = idx & 15;
                pb[i] = *reinterpret_cast<const float4*>(W + (size_t)(k0 + kk) * DF + n0 + c4 * 4);
            }
        }
        const float (*Ac)[132] = As[cur];
        const float (*Bc)[68] = Bs[cur];
#pragma unroll
        for (int k = 0; k < 16; k++) {
            float av[8];
            *(float4*)&av[0] = *(const float4*)&Ac[k][ty * 8];
            *(float4*)&av[4] = *(const float4*)&Ac[k][ty * 8 + 4];
            ull bv[4];
#pragma unroll
            for (int u = 0; u < 4; u++)
                bv[u] = *reinterpret_cast<const ull*>(&Bc[k][tx * 8 + 2 * u]);
#pragma unroll
            for (int i = 0; i < 8; i++) {
                ull ai = pack2(av[i], av[i]);
#pragma unroll
                for (int u = 0; u < 4; u++) acc[i][u] = ffma2(ai, bv[u], acc[i][u]);
            }
        }
        if (hn) {
            int nb = cur ^ 1;
#pragma unroll
            for (int q = 0; q < 4; q++) {
                As[nb][q * 4 + 0][tid] = pa[q].x; As[nb][q * 4 + 1][tid] = pa[q].y;
                As[nb][q * 4 + 2][tid] = pa[q].z; As[nb][q * 4 + 3][tid] = pa[q].w;
            }
#pragma unroll
            for (int i = 0; i < 2; i++) {
                int idx = tid + i * 128;
                int kk = idx >> 4, c4 = idx & 15;
                *reinterpret_cast<float4*>(&Bs[nb][kk][c4 * 4]) = pb[i];
            }
            __syncthreads();
            cur = nb;
        }
    }
    float* out = g_parts + (size_t)sp * MKF * DF;
#pragma unroll
    for (int i = 0; i < 8; i++) {
        int r = m0 + ty * 8 + i;
#pragma unroll
        for (int u = 0; u < 4; u++)
            *reinterpret_cast<ull*>(out + (size_t)r * DF + n0 + tx * 8 + 2 * u) = acc[i][u];
    }
}

__global__ void k_reduce_kf() {
    int i = blockIdx.x * 256 + threadIdx.x;
    if (i >= MKF * DF) return;
    const size_t T = (size_t)MKF * DF;
    float s = 0.f;
#pragma unroll
    for (int p = 0; p < SPLITS_KF; p++) s += g_parts[p * T + i];
    g_KF[i] = s;
}

// ============================================================
// Persistent-chain phase bodies (double-buffered BM=64 BN=32)
// ============================================================
__device__ __forceinline__ void phase_aul(int bid, float As[2][16][68], float Bs2[2][16][72]) {
    const int tid = threadIdx.x;
    const int n0 = (bid % 13) * 32;
    const int m0 = ((bid / 13) % 7) * 64;
    const int sp = bid / 91;
    const int kt0 = sp * 10, kt1 = kt0 + 10;
    const int ty = tid >> 4, tx = tid & 15;
    const int ar = tid >> 2, aq = tid & 3;
    int rr0 = m0 + ar; if (rr0 > MS - 1) rr0 = MS - 1;
    int rr1 = m0 + ar + 32; if (rr1 > MS - 1) rr1 = MS - 1;
    int nn = n0 + ar; if (nn > MS - 1) nn = MS - 1;
    ull acc[4][2];
#pragma unroll
    for (int i = 0; i < 4; i++) { acc[i][0] = 0ull; acc[i][1] = 0ull; }

    float4 pa0, pa1, pb;
    {
        const int k0 = kt0 * 16;
        pa0 = *reinterpret_cast<const float4*>(g_KF + (size_t)rr0 * DF + k0 + aq * 4);
        pa1 = *reinterpret_cast<const float4*>(g_KF + (size_t)rr1 * DF + k0 + aq * 4);
        pb  = *reinterpret_cast<const float4*>(g_KF + (size_t)nn * DF + k0 + aq * 4);
    }
    int cur = 0;
    {
        As[0][aq * 4 + 0][ar] = pa0.x; As[0][aq * 4 + 1][ar] = pa0.y;
        As[0][aq * 4 + 2][ar] = pa0.z; As[0][aq * 4 + 3][ar] = pa0.w;
        As[0][aq * 4 + 0][ar + 32] = pa1.x; As[0][aq * 4 + 1][ar + 32] = pa1.y;
        As[0][aq * 4 + 2][ar + 32] = pa1.z; As[0][aq * 4 + 3][ar + 32] = pa1.w;
        *reinterpret_cast<ull*>(&Bs2[0][aq * 4 + 0][ar * 2]) = pack2(pb.x, pb.x);
        *reinterpret_cast<ull*>(&Bs2[0][aq * 4 + 1][ar * 2]) = pack2(pb.y, pb.y);
        *reinterpret_cast<ull*>(&Bs2[0][aq * 4 + 2][ar * 2]) = pack2(pb.z, pb.z);
        *reinterpret_cast<ull*>(&Bs2[0][aq * 4 + 3][ar * 2]) = pack2(pb.w, pb.w);
    }
    __syncthreads();

    for (int kt = kt0; kt < kt1; ++kt) {
        const bool hn = (kt + 1 < kt1);
        if (hn) {
            const int k0 = (kt + 1) * 16;
            pa0 = *reinterpret_cast<const float4*>(g_KF + (size_t)rr0 * DF + k0 + aq * 4);
            pa1 = *reinterpret_cast<const float4*>(g_KF + (size_t)rr1 * DF + k0 + aq * 4);
            pb  = *reinterpret_cast<const float4*>(g_KF + (size_t)nn * DF + k0 + aq * 4);
        }
        const float (*Ac)[68] = As[cur];
        const float (*Bc)[72] = Bs2[cur];
#pragma unroll
        for (int k = 0; k < 16; k++) {
            float4 a0 = *(const float4*)&Ac[k][ty * 8];
            float4 a1 = *(const float4*)&Ac[k][ty * 8 + 4];
            float4 bq = *(const float4*)&Bc[k][tx * 4];
            ull ap[4] = { pack2(a0.x, a0.y), pack2(a0.z, a0.w),
                          pack2(a1.x, a1.y), pack2(a1.z, a1.w) };
            ull b0 = pack2(bq.x, bq.y), b1 = pack2(bq.z, bq.w);
#pragma unroll
            for (int i = 0; i < 4; i++) {
                acc[i][0] = ffma2(ap[i], b0, acc[i][0]);
                acc[i][1] = ffma2(ap[i], b1, acc[i][1]);
            }
        }
        if (hn) {
            int nb = cur ^ 1;
            As[nb][aq * 4 + 0][ar] = pa0.x; As[nb][aq * 4 + 1][ar] = pa0.y;
            As[nb][aq * 4 + 2][ar] = pa0.z; As[nb][aq * 4 + 3][ar] = pa0.w;
            As[nb][aq * 4 + 0][ar + 32] = pa1.x; As[nb][aq * 4 + 1][ar + 32] = pa1.y;
            As[nb][aq * 4 + 2][ar + 32] = pa1.z; As[nb][aq * 4 + 3][ar + 32] = pa1.w;
            *reinterpret_cast<ull*>(&Bs2[nb][aq * 4 + 0][ar * 2]) = pack2(pb.x, pb.x);
            *reinterpret_cast<ull*>(&Bs2[nb][aq * 4 + 1][ar * 2]) = pack2(pb.y, pb.y);
            *reinterpret_cast<ull*>(&Bs2[nb][aq * 4 + 2][ar * 2]) = pack2(pb.z, pb.z);
            *reinterpret_cast<ull*>(&Bs2[nb][aq * 4 + 3][ar * 2]) = pack2(pb.w, pb.w);
            __syncthreads();
            cur = nb;
        }
    }
    float* out = g_parts + (size_t)sp * MS * MS;
    int c = n0 + tx * 2;
    if (c < MS) {
#pragma unroll
        for (int i = 0; i < 4; i++) {
            int r0 = m0 + ty * 8 + 2 * i;
            if (r0 < MS) {
                float2 f0 = u2f(acc[i][0]);
                float2 f1 = u2f(acc[i][1]);
                *reinterpret_cast<ull*>(out + (size_t)r0 * MS + c) = pack2(f0.x, f1.x);
                *reinterpret_cast<ull*>(out + (size_t)(r0 + 1) * MS + c) = pack2(f0.y, f1.y);
            }
        }
    }
}

__device__ __forceinline__ void phase_a2(int bid, float As[2][16][68], float Bs2[2][16][72]) {
    const int tid = threadIdx.x;
    const int n0 = (bid % 13) * 32;
    const int m0 = ((bid / 13) % 7) * 64;
    const int sp = bid / 91;
    const int kt0 = sp * 25 / 4, kt1 = (sp + 1) * 25 / 4;
    const int ty = tid >> 4, tx = tid & 15;
    const int ar = tid >> 2, aq = tid & 3;
    int rr0 = m0 + ar; if (rr0 > MS - 1) rr0 = MS - 1;
    int rr1 = m0 + ar + 32; if (rr1 > MS - 1) rr1 = MS - 1;
    const int bkk = tid >> 3, bc4 = tid & 7;
    const int bc = n0 + bc4 * 4;
    ull acc[4][2];
#pragma unroll
    for (int i = 0; i < 4; i++) { acc[i][0] = 0ull; acc[i][1] = 0ull; }

    float4 pa0, pa1, pb;
    {
        const int k0 = kt0 * 16;
        pa0 = *reinterpret_cast<const float4*>(g_aul + (size_t)rr0 * MS + k0 + aq * 4);
        pa1 = *reinterpret_cast<const float4*>(g_aul + (size_t)rr1 * MS + k0 + aq * 4);
        pb = make_float4(0.f, 0.f, 0.f, 0.f);
        if (bc < MS) pb = *reinterpret_cast<const float4*>(g_aul + (size_t)(k0 + bkk) * MS + bc);
    }
    int cur = 0;
    {
        As[0][aq * 4 + 0][ar] = pa0.x; As[0][aq * 4 + 1][ar] = pa0.y;
        As[0][aq * 4 + 2][ar] = pa0.z; As[0][aq * 4 + 3][ar] = pa0.w;
        As[0][aq * 4 + 0][ar + 32] = pa1.x; As[0][aq * 4 + 1][ar + 32] = pa1.y;
        As[0][aq * 4 + 2][ar + 32] = pa1.z; As[0][aq * 4 + 3][ar + 32] = pa1.w;
        *reinterpret_cast<float4*>(&Bs2[0][bkk][bc4 * 8]) = make_float4(pb.x, pb.x, pb.y, pb.y);
        *reinterpret_cast<float4*>(&Bs2[0][bkk][bc4 * 8 + 4]) = make_float4(pb.z, pb.z, pb.w, pb.w);
    }
    __syncthreads();

    for (int kt = kt0; kt < kt1; ++kt) {
        const bool hn = (kt + 1 < kt1);
        if (hn) {
            const int k0 = (kt + 1) * 16;
            pa0 = *reinterpret_cast<const float4*>(g_aul + (size_t)rr0 * MS + k0 + aq * 4);
            pa1 = *reinterpret_cast<const float4*>(g_aul + (size_t)rr1 * MS + k0 + aq * 4);
            pb = make_float4(0.f, 0.f, 0.f, 0.f);
            if (bc < MS) pb = *reinterpret_cast<const float4*>(g_aul + (size_t)(k0 + bkk) * MS + bc);
        }
        const float (*Ac)[68] = As[cur];
        const float (*Bc)[72] = Bs2[cur];
#pragma unroll
        for (int k = 0; k < 16; k++) {
            float4 a0 = *(const float4*)&Ac[k][ty * 8];
            float4 a1 = *(const float4*)&Ac[k][ty * 8 + 4];
            float4 bq = *(const float4*)&Bc[k][tx * 4];
            ull ap[4] = { pack2(a0.x, a0.y), pack2(a0.z, a0.w),
                          pack2(a1.x, a1.y), pack2(a1.z, a1.w) };
            ull b0 = pack2(bq.x, bq.y), b1 = pack2(bq.z, bq.w);
#pragma unroll
            for (int i = 0; i < 4; i++) {
                acc[i][0] = ffma2(ap[i], b0, acc[i][0]);
                acc[i][1] = ffma2(ap[i], b1, acc[i][1]);
            }
        }
        if (hn) {
            int nb = cur ^ 1;
            As[nb][aq * 4 + 0][ar] = pa0.x; As[nb][aq * 4 + 1][ar] = pa0.y;
            As[nb][aq * 4 + 2][ar] = pa0.z; As[nb][aq * 4 + 3][ar] = pa0.w;
            As[nb][aq * 4 + 0][ar + 32] = pa1.x; As[nb][aq * 4 + 1][ar + 32] = pa1.y;
            As[nb][aq * 4 + 2][ar + 32] = pa1.z; As[nb][aq * 4 + 3][ar + 32] = pa1.w;
            *reinterpret_cast<float4*>(&Bs2[nb][bkk][bc4 * 8]) = make_float4(pb.x, pb.x, pb.y, pb.y);
            *reinterpret_cast<float4*>(&Bs2[nb][bkk][bc4 * 8 + 4]) = make_float4(pb.z, pb.z, pb.w, pb.w);
            __syncthreads();
            cur = nb;
        }
    }
    float* out = g_M[0][sp];
    int c = n0 + tx * 2;
    if (c < MS) {
#pragma unroll
        for (int i = 0; i < 4; i++) {
            int r0 = m0 + ty * 8 + 2 * i;
            if (r0 < MS) {
                float2 f0 = u2f(acc[i][0]);
                float2 f1 = u2f(acc[i][1]);
                *reinterpret_cast<ull*>(out + (size_t)r0 * MS + c) = pack2(f0.x, f1.x);
                *reinterpret_cast<ull*>(out + (size_t)(r0 + 1) * MS + c) = pack2(f0.y, f1.y);
            }
        }
    }
}

__device__ __forceinline__ void phase_iter(int bid, int first, int src, int dst,
                                           float As[2][16][68], float Bs2[2][16][72]) {
    const int tid = threadIdx.x;
    const int n0 = (bid % 13) * 32;
    const int m0 = ((bid / 13) % 7) * 64;
    const int sp = bid / 91;
    const int kt0 = sp * 25 / 4, kt1 = (sp + 1) * 25 / 4;
    const int ty = tid >> 4, tx = tid & 15;
    const float* __restrict__ Ms = g_M[src][0];
    const int PS = MS * CW;
    const int ar = tid >> 2, aq = tid & 3;
    int rr0 = m0 + ar; if (rr0 > MS - 1) rr0 = MS - 1;
    int rr1 = m0 + ar + 32; if (rr1 > MS - 1) rr1 = MS - 1;
    const int bkk = tid >> 3, bc4 = tid & 7;
    const int bc = n0 + bc4 * 4;
    ull acc[4][2];
#pragma unroll
    for (int i = 0; i < 4; i++) { acc[i][0] = 0ull; acc[i][1] = 0ull; }

    float4 pa0, pa1, pb;
    // .cg on Ms loads: g_M is rewritten across phases; L1 is non-coherent.
#define LOAD_A(dst4, rr, kt_)  do {                                             \
        const int k0_ = (kt_) * 16;                                             \
        if (first) {                                                            \
            dst4 = *reinterpret_cast<const float4*>(g_Bb + (size_t)(rr) * MS + k0_ + aq * 4); \
        } else {                                                                \
            const float* base = Ms + (size_t)(rr) * CW + k0_ + aq * 4;          \
            float4 v0 = __ldcg((const float4*)(base));                          \
            float4 v1 = __ldcg((const float4*)(base + PS));                     \
            float4 v2 = __ldcg((const float4*)(base + 2 * PS));                 \
            float4 v3 = __ldcg((const float4*)(base + 3 * PS));                 \
            dst4 = make_float4(v0.x + v1.x + v2.x + v3.x, v0.y + v1.y + v2.y + v3.y, \
                               v0.z + v1.z + v2.z + v3.z, v0.w + v1.w + v2.w + v3.w); \
        }                                                                       \
    } while (0)
#define LOAD_B(dst4, kt_)  do {                                                 \
        const int kr_ = (kt_) * 16 + bkk;                                       \
        if (first) {                                                            \
            if (bc < MS) dst4 = *reinterpret_cast<const float4*>(g_Bb + (size_t)kr_ * MS + bc); \
            else         dst4 = *reinterpret_cast<const float4*>(g_Xa + (size_t)kr_ * NRHS + (bc - MS)); \
        } else {                                                                \
            const float* base = Ms + (size_t)kr_ * CW + bc;                     \
            float4 v0 = __ldcg((const float4*)(base));                          \
            float4 v1 = __ldcg((const float4*)(base + PS));                     \
            float4 v2 = __ldcg((const float4*)(base + 2 * PS));                 \
            float4 v3 = __ldcg((const float4*)(base + 3 * PS));                 \
            dst4 = make_float4(v0.x + v1.x + v2.x + v3.x, v0.y + v1.y + v2.y + v3.y, \
                               v0.z + v1.z + v2.z + v3.z, v0.w + v1.w + v2.w + v3.w); \
        }                                                                       \
    } while (0)

    LOAD_A(pa0, rr0, kt0);
    LOAD_A(pa1, rr1, kt0);
    LOAD_B(pb, kt0);
    int cur = 0;
    {
        As[0][aq * 4 + 0][ar] = pa0.x; As[0][aq * 4 + 1][ar] = pa0.y;
        As[0][aq * 4 + 2][ar] = pa0.z; As[0][aq * 4 + 3][ar] = pa0.w;
        As[0][aq * 4 + 0][ar + 32] = pa1.x; As[0][aq * 4 + 1][ar + 32] = pa1.y;
        As[0][aq * 4 + 2][ar + 32] = pa1.z; As[0][aq * 4 + 3][ar + 32] = pa1.w;
        *reinterpret_cast<float4*>(&Bs2[0][bkk][bc4 * 8]) = make_float4(pb.x, pb.x, pb.y, pb.y);
        *reinterpret_cast<float4*>(&Bs2[0][bkk][bc4 * 8 + 4]) = make_float4(pb.z, pb.z, pb.w, pb.w);
    }
    __syncthreads();

    for (int kt = kt0; kt < kt1; ++kt) {
        const bool hn = (kt + 1 < kt1);
        if (hn) {
            LOAD_A(pa0, rr0, kt + 1);
            LOAD_A(pa1, rr1, kt + 1);
            LOAD_B(pb, kt + 1);
        }
        const float (*Ac)[68] = As[cur];
        const float (*Bc)[72] = Bs2[cur];
#pragma unroll
        for (int k = 0; k < 16; k++) {
            float4 a0 = *(const float4*)&Ac[k][ty * 8];
            float4 a1 = *(const float4*)&Ac[k][ty * 8 + 4];
            float4 bq = *(const float4*)&Bc[k][tx * 4];
            ull ap[4] = { pack2(a0.x, a0.y), pack2(a0.z, a0.w),
                          pack2(a1.x, a1.y), pack2(a1.z, a1.w) };
            ull b0 = pack2(bq.x, bq.y), b1 = pack2(bq.z, bq.w);
#pragma unroll
            for (int i = 0; i < 4; i++) {
                acc[i][0] = ffma2(ap[i], b0, acc[i][0]);
                acc[i][1] = ffma2(ap[i], b1, acc[i][1]);
            }
        }
        if (hn) {
            int nb = cur ^ 1;
            As[nb][aq * 4 + 0][ar] = pa0.x; As[nb][aq * 4 + 1][ar] = pa0.y;
            As[nb][aq * 4 + 2][ar] = pa0.z; As[nb][aq * 4 + 3][ar] = pa0.w;
            As[nb][aq * 4 + 0][ar + 32] = pa1.x; As[nb][aq * 4 + 1][ar + 32] = pa1.y;
            As[nb][aq * 4 + 2][ar + 32] = pa1.z; As[nb][aq * 4 + 3][ar + 32] = pa1.w;
            *reinterpret_cast<float4*>(&Bs2[nb][bkk][bc4 * 8]) = make_float4(pb.x, pb.x, pb.y, pb.y);
            *reinterpret_cast<float4*>(&Bs2[nb][bkk][bc4 * 8 + 4]) = make_float4(pb.z, pb.z, pb.w, pb.w);
            __syncthreads();
            cur = nb;
        }
    }
#undef LOAD_A
#undef LOAD_B
    float* __restrict__ outp = g_M[dst][sp];
    int c = n0 + tx * 2;
#pragma unroll
    for (int i = 0; i < 4; i++) {
        int r0 = m0 + ty * 8 + 2 * i;
        if (r0 < MS) {
            float2 f0 = u2f(acc[i][0]);
            float2 f1 = u2f(acc[i][1]);
            float x00 = f0.x, x10 = f0.y, x01 = f1.x, x11 = f1.y;
            if (sp == 0 && c >= MS) {
                if (first) {
                    x00 += g_Xa[r0 * NRHS + (c - MS)];
                    x01 += g_Xa[r0 * NRHS + (c - MS) + 1];
                    x10 += g_Xa[(r0 + 1) * NRHS + (c - MS)];
                    x11 += g_Xa[(r0 + 1) * NRHS + (c - MS) + 1];
                } else {
                    const float* b0p = Ms + (size_t)r0 * CW + c;
                    const float* b1p = Ms + (size_t)(r0 + 1) * CW + c;
#pragma unroll
                    for (int p = 0; p < 4; p++) {
                        x00 += __ldcg(b0p + p * PS); x01 += __ldcg(b0p + p * PS + 1);
                        x10 += __ldcg(b1p + p * PS); x11 += __ldcg(b1p + p * PS + 1);
                    }
                }
            }
            *reinterpret_cast<ull*>(outp + (size_t)r0 * CW + c) = pack2(x00, x01);
            *reinterpret_cast<ull*>(outp + (size_t)(r0 + 1) * CW + c) = pack2(x10, x11);
        }
    }
}

// ============================================================
// Persistent chain kernel: aul .. logits in one launch
// ============================================================
__global__ __launch_bounds__(128) void k_chain(float* __restrict__ out,
                                               const float* __restrict__ gamma) {
    __shared__ float As[2][16][68];
    __shared__ float Bs2[2][16][72];
    __shared__ float red[128];
    __shared__ float s_om;
    const int bid = blockIdx.x;
    const int tid = threadIdx.x;
    const int gtid = bid * 128 + tid;

    // C0: aul split-K GEMM -> g_parts
    phase_aul(bid, As, Bs2);
    gbar(0);

    // C1: reduce aul partials -> g_aul (+50 I)
    {
        const int T = MS * MS;
        for (int i = gtid; i < T; i += NT_CH) {
            float s = __ldcg(&g_parts[i]) + __ldcg(&g_parts[T + i])
                    + __ldcg(&g_parts[2 * T + i]) + __ldcg(&g_parts[3 * T + i]);
            int r = i / MS, c = i - r * MS;
            if (r == c) s += 50.0f;
            g_aul[i] = s;
        }
    }
    gbar(1);

    // C2: A2 = aul@aul split-K -> g_M[0] planes
    phase_a2(bid, As, Bs2);
    gbar(2);

    // C3: sum A2 partials -> g_A2, Frobenius^2 block partials -> g_red
    {
        float fs = 0.f;
        for (int i = gtid; i < MS * MS; i += NT_CH) {
            float v = __ldcg(&g_M[0][0][i]) + __ldcg(&g_M[0][1][i])
                    + __ldcg(&g_M[0][2][i]) + __ldcg(&g_M[0][3][i]);
            g_A2[i] = v;
            fs += v * v;
        }
        red[tid] = fs; __syncthreads();
        for (int o = 64; o > 0; o >>= 1) {
            if (tid < o) red[tid] += red[tid + o];
            __syncthreads();
        }
        if (tid == 0) g_red[bid] = red[0];
    }
    gbar(3);

    // C4: omega; B^2; X1 (every block computes omega redundantly)
    {
        float t = 0.f;
        for (int i = tid; i < GRID_CH; i += 128) t += g_red[i];
        red[tid] = t; __syncthreads();
        for (int o = 64; o > 0; o >>= 1) {
            if (tid < o) red[tid] += red[tid + o];
            __syncthreads();
        }
        float b = sqrtf(sqrtf(red[0])) * 1.0001f;
        if (!(b > 51.f)) b = 51.f;
        float om = 2.0f / (b + 50.0f);
        if (tid == 0) s_om = om;
        for (int i = gtid; i < MS * MS + MS * NRHS; i += NT_CH) {
            if (i < MS * MS) {
                int r = i / MS, c = i - r * MS;
                float a = g_aul[i] * om;
                float a2 = g_A2[i] * om * om;
                float d = (r == c) ? 1.f : 0.f;
                g_Bb[i] = d - 2.f * a + a2;
            } else {
                int idx = i - MS * MS;
                int j = idx >> 4, c = idx & 15;
                float s = ((j / NSUP) == c) ? 2.f : 0.f;
                const float* row = g_aul + (size_t)j * MS + c * NSUP;
                float u = 0.f;
#pragma unroll
                for (int q = 0; q < NSUP; q++) u += row[q];
                g_Xa[idx] = s - u * om;
            }
        }
        __syncthreads();   // s_om visible for later phases
    }
    gbar(4);

    // C5..C11: 7 chain iterations (512 Neumann terms after final xonly)
    phase_iter(bid, 1, 0, 0, As, Bs2); gbar(5);
    phase_iter(bid, 0, 0, 1, As, Bs2); gbar(6);
    phase_iter(bid, 0, 1, 0, As, Bs2); gbar(7);
    phase_iter(bid, 0, 0, 1, As, Bs2); gbar(8);
    phase_iter(bid, 0, 1, 0, As, Bs2); gbar(9);
    phase_iter(bid, 0, 0, 1, As, Bs2); gbar(10);
    phase_iter(bid, 0, 1, 0, As, Bs2); gbar(11);

    // C12: materialize B^256 -> g_Ba, X -> g_Xb from g_M[0] partials
    {
        const int PS = MS * CW;
        const float* Ms = g_M[0][0];
        for (int i = gtid; i < MS * CW; i += NT_CH) {
            float s = __ldcg(Ms + i) + __ldcg(Ms + i + PS)
                    + __ldcg(Ms + i + 2 * PS) + __ldcg(Ms + i + 3 * PS);
            int r = i / CW, c = i - r * CW;
            if (c < MS) g_Ba[(size_t)r * MS + c] = s;
            else g_Xb[r * NRHS + (c - MS)] = s;
        }
    }
    gbar(12);

    // C13: Xa = Xb + B^256 @ Xb
    if (gtid < MS * NRHS) {
        int j = gtid >> 4, c = gtid & 15;
        const float* br = g_Ba + (size_t)j * MS;
        float s = g_Xb[gtid];
#pragma unroll 4
        for (int k = 0; k < MS; k++) s = fmaf(br[k], g_Xb[k * NRHS + c], s);
        g_Xa[gtid] = s;
    }
    gbar(13);

    // C14: w[c][d] = om * sum_j Xa[j][c] * K[j][d]
    if (gtid < NRHS * DF) {
        int c = gtid / DF, d = gtid - c * DF;
        float s = 0.f;
#pragma unroll 4
        for (int j = 0; j < MS; j++)
            s = fmaf(__ldcg(&g_Xa[j * NRHS + c]), g_KF[(size_t)j * DF + d], s);
        g_w[gtid] = s * s_om;
    }
    gbar(14);

    // C15: logits[q][c] = -gamma * sum_d f_x[q][d] * w[c][d]
    if (gtid < MQ * NRHS) {
        int q = gtid >> 4, c = gtid & 15;
        const float4* f = reinterpret_cast<const float4*>(g_KF + (size_t)(MS + q) * DF);
        const float4* wr = reinterpret_cast<const float4*>(g_w + (size_t)c * DF);
        float s = 0.f;
#pragma unroll 4
        for (int d = 0; d < DF / 4; d++) {
            float4 a = f[d], b = wr[d];
            s = fmaf(a.x, b.x, s); s = fmaf(a.y, b.y, s);
            s = fmaf(a.z, b.z, s); s = fmaf(a.w, b.w, s);
        }
        out[gtid] = -gamma[0] * s;
    }
}

// ============================================================
extern "C" void kernel_launch(void* const* d_in, const int* in_sizes, int n_in,
                              void* d_out, int out_size) {
    const float* S = (const float*)d_in[0];
    const float* Qm = (const float*)d_in[1];
    const float* W = (const float*)d_in[2];
    const float* gamma = (const float*)d_in[3];
    float* out = (float*)d_out;
    (void)in_sizes; (void)n_in; (void)out_size;

    k_gemm_kf<<<dim3(10, 5, SPLITS_KF), 128>>>(S, Qm, W);
    k_reduce_kf<<<(MKF * DF + 255) / 256, 256>>>();
    k_chain<<<GRID_CH, 128>>>(out, gamma);
}